// round 1
// baseline (speedup 1.0000x reference)
#include <cuda_runtime.h>

#define BB 256
#define TT 2048
#define HH 64
#define NCHUNK (TT / 32)

// scratch for per-(dir,b,t) fc dot products: 4 MB
__device__ float g_dot[2 * BB * TT];

typedef unsigned long long ull;

__device__ __forceinline__ ull pack2(float lo, float hi) {
    ull r; asm("mov.b64 %0, {%1, %2};" : "=l"(r) : "f"(lo), "f"(hi)); return r;
}
__device__ __forceinline__ void unpack2(ull v, float& lo, float& hi) {
    asm("mov.b64 {%0, %1}, %2;" : "=f"(lo), "=f"(hi) : "l"(v));
}
__device__ __forceinline__ ull fma2(ull a, ull b, ull c) {
    ull d; asm("fma.rn.f32x2 %0, %1, %2, %3;" : "=l"(d) : "l"(a), "l"(b), "l"(c)); return d;
}
__device__ __forceinline__ ull add2(ull a, ull b) {
    ull d; asm("add.rn.f32x2 %0, %1, %2;" : "=l"(d) : "l"(a), "l"(b)); return d;
}
// tanh(z) = 1 - 2/(1 + exp(2z)); exp via ex2.approx, recip via rcp.approx.
// Safe at +/- inf (no NaN), abs err ~3e-7.
__device__ __forceinline__ float fast_tanh(float z) {
    float e, r;
    asm("ex2.approx.f32 %0, %1;" : "=f"(e) : "f"(z * 2.8853900817779268f));
    asm("rcp.approx.f32 %0, %1;" : "=f"(r) : "f"(e + 1.0f));
    return fmaf(-2.0f, r, 1.0f);
}

__global__ __launch_bounds__(128, 1) void birnn_main(
    const float* __restrict__ x,
    const float* __restrict__ w_ih_f, const float* __restrict__ w_hh_f,
    const float* __restrict__ b_ih_f, const float* __restrict__ b_hh_f,
    const float* __restrict__ w_ih_b, const float* __restrict__ w_hh_b,
    const float* __restrict__ b_ih_b, const float* __restrict__ b_hh_b,
    const float* __restrict__ w_fc,
    float* __restrict__ out)
{
    __shared__ __align__(16) float2 hbuf[4][2][HH];  // per-warp double-buffered h, splat pairs
    __shared__ float pbuf[4][32 * 33];               // per-warp fc-dot partials (padded)

    const int wid  = threadIdx.x >> 5;
    const int lane = threadIdx.x & 31;
    const int chain = blockIdx.x * 4 + wid;   // 0..511
    const int dir = chain >> 8;               // 0 = fwd, 1 = bwd
    const int b   = chain & 255;

    const float* wih = dir ? w_ih_b : w_ih_f;
    const float* whh = dir ? w_hh_b : w_hh_f;
    const float* bih = dir ? b_ih_b : b_ih_f;
    const float* bhh = dir ? b_hh_b : b_hh_f;

    const int i0 = lane, i1 = lane + 32;

    // --- load recurrent weights into registers as f32x2 pairs (w[i0][j], w[i1][j]) ---
    ull w2[HH];
#pragma unroll
    for (int jj = 0; jj < 16; jj++) {
        float4 a = reinterpret_cast<const float4*>(whh + i0 * HH)[jj];
        float4 c = reinterpret_cast<const float4*>(whh + i1 * HH)[jj];
        w2[4 * jj + 0] = pack2(a.x, c.x);
        w2[4 * jj + 1] = pack2(a.y, c.y);
        w2[4 * jj + 2] = pack2(a.z, c.z);
        w2[4 * jj + 3] = pack2(a.w, c.w);
    }
    const ull wih2  = pack2(wih[i0], wih[i1]);
    const ull bias2 = pack2(bih[i0] + bhh[i0], bih[i1] + bhh[i1]);
    const float wfa = w_fc[i0], wfb = w_fc[i1];

    // h = 0 into phase 0
    hbuf[wid][0][i0] = make_float2(0.f, 0.f);
    hbuf[wid][0][i1] = make_float2(0.f, 0.f);

    float h0 = 0.f, h1 = 0.f;
    const float* xb = x + b * TT;

    // prefetch x for chunk 0
    float xcur = xb[dir ? (TT - 32 + lane) : lane];

    for (int chunk = 0; chunk < NCHUNK; chunk++) {
        const int tb = dir ? (TT - 1 - chunk * 32) : (chunk * 32);
        // prefetch next chunk's x (clamped for last chunk)
        int nc = (chunk + 1 < NCHUNK) ? (chunk + 1) : chunk;
        float xnext = xb[dir ? (TT - 1 - nc * 32 - 31 + lane) : (nc * 32 + lane)];

#define STEP(SS, RD, WR)                                                          \
        {                                                                         \
            const int s = (SS);                                                   \
            float xs = __shfl_sync(0xffffffffu, xcur, dir ? (31 - s) : s);        \
            ull acc0 = fma2(wih2, pack2(xs, xs), bias2);                          \
            ull acc1 = 0, acc2v = 0, acc3 = 0, acc4 = 0,                          \
                acc5 = 0, acc6 = 0, acc7 = 0;                                     \
            __syncwarp();                                                         \
            const ulonglong2* hr =                                                \
                reinterpret_cast<const ulonglong2*>(&hbuf[wid][RD][0]);           \
            _Pragma("unroll")                                                     \
            for (int k = 0; k < 8; k++) {                                         \
                ulonglong2 v0 = hr[4 * k + 0];                                    \
                ulonglong2 v1 = hr[4 * k + 1];                                    \
                ulonglong2 v2 = hr[4 * k + 2];                                    \
                ulonglong2 v3 = hr[4 * k + 3];                                    \
                acc0  = fma2(w2[8 * k + 0], v0.x, acc0);                          \
                acc1  = fma2(w2[8 * k + 1], v0.y, acc1);                          \
                acc2v = fma2(w2[8 * k + 2], v1.x, acc2v);                         \
                acc3  = fma2(w2[8 * k + 3], v1.y, acc3);                          \
                acc4  = fma2(w2[8 * k + 4], v2.x, acc4);                          \
                acc5  = fma2(w2[8 * k + 5], v2.y, acc5);                          \
                acc6  = fma2(w2[8 * k + 6], v3.x, acc6);                          \
                acc7  = fma2(w2[8 * k + 7], v3.y, acc7);                          \
            }                                                                     \
            ull z2 = add2(add2(add2(acc0, acc1), add2(acc2v, acc3)),              \
                          add2(add2(acc4, acc5), add2(acc6, acc7)));              \
            float z0, z1; unpack2(z2, z0, z1);                                    \
            h0 = fast_tanh(z0);                                                   \
            h1 = fast_tanh(z1);                                                   \
            hbuf[wid][WR][i0] = make_float2(h0, h0);                              \
            hbuf[wid][WR][i1] = make_float2(h1, h1);                              \
            pbuf[wid][s * 33 + lane] = fmaf(h1, wfb, h0 * wfa);                   \
        }

#pragma unroll 1
        for (int s2 = 0; s2 < 16; s2++) {
            STEP(2 * s2,     0, 1)
            STEP(2 * s2 + 1, 1, 0)
        }
#undef STEP

        __syncwarp();
        // transpose-reduce fc partials: lane l produces dot for step s=l of this chunk
        {
            const float* pr = &pbuf[wid][lane * 33];
            float v[32];
#pragma unroll
            for (int j = 0; j < 32; j++) v[j] = pr[j];
#pragma unroll
            for (int st = 16; st >= 1; st >>= 1)
#pragma unroll
                for (int j = 0; j < 32; j++)
                    if (j < st) v[j] = v[j] + v[j + st];
            int tt = dir ? (tb - lane) : (tb + lane);
            g_dot[dir * (BB * TT) + b * TT + tt] = v[0];
        }
        xcur = xnext;
    }

    // final hidden state h_n[dir][b][h] after y block
    out[BB * TT + dir * (BB * HH) + b * HH + i0] = h0;
    out[BB * TT + dir * (BB * HH) + b * HH + i1] = h1;
}

__global__ void birnn_combine(const float* __restrict__ b_fc, float* __restrict__ out)
{
    int idx = blockIdx.x * blockDim.x + threadIdx.x;  // 0 .. B*T-1
    float z = 0.5f * (g_dot[idx] + g_dot[BB * TT + idx]) + b_fc[0];
    // sigmoid(z) = 1/(1+exp(-z))
    float e, r;
    asm("ex2.approx.f32 %0, %1;" : "=f"(e) : "f"(-1.4426950408889634f * z));
    asm("rcp.approx.f32 %0, %1;" : "=f"(r) : "f"(1.0f + e));
    out[idx] = r;
}

extern "C" void kernel_launch(void* const* d_in, const int* in_sizes, int n_in,
                              void* d_out, int out_size)
{
    const float* x      = (const float*)d_in[0];
    const float* w_ih_f = (const float*)d_in[1];
    const float* w_hh_f = (const float*)d_in[2];
    const float* b_ih_f = (const float*)d_in[3];
    const float* b_hh_f = (const float*)d_in[4];
    const float* w_ih_b = (const float*)d_in[5];
    const float* w_hh_b = (const float*)d_in[6];
    const float* b_ih_b = (const float*)d_in[7];
    const float* b_hh_b = (const float*)d_in[8];
    const float* w_fc   = (const float*)d_in[9];
    const float* b_fc   = (const float*)d_in[10];
    float* out = (float*)d_out;

    birnn_main<<<128, 128>>>(x, w_ih_f, w_hh_f, b_ih_f, b_hh_f,
                             w_ih_b, w_hh_b, b_ih_b, b_hh_b, w_fc, out);
    birnn_combine<<<(BB * TT) / 256, 256>>>(b_fc, out);
}

// round 3
// speedup vs baseline: 1.3551x; 1.3551x over previous
#include <cuda_runtime.h>

#define BB 256
#define TT 2048
#define HH 64
#define NCHUNK (TT / 32)

// scratch for per-(dir,b,t) fc dot products: 4 MB
__device__ float g_dot[2 * BB * TT];

typedef unsigned long long ull;

__device__ __forceinline__ ull pack2(float lo, float hi) {
    ull r; asm("mov.b64 %0, {%1, %2};" : "=l"(r) : "f"(lo), "f"(hi)); return r;
}
__device__ __forceinline__ void unpack2(ull v, float& lo, float& hi) {
    asm("mov.b64 {%0, %1}, %2;" : "=f"(lo), "=f"(hi) : "l"(v));
}
__device__ __forceinline__ ull fma2(ull a, ull b, ull c) {
    ull d; asm("fma.rn.f32x2 %0, %1, %2, %3;" : "=l"(d) : "l"(a), "l"(b), "l"(c)); return d;
}
__device__ __forceinline__ ull add2(ull a, ull b) {
    ull d; asm("add.rn.f32x2 %0, %1, %2;" : "=l"(d) : "l"(a), "l"(b)); return d;
}
__device__ __forceinline__ float tanh_fast(float z) {
    float r; asm("tanh.approx.f32 %0, %1;" : "=f"(r) : "f"(z)); return r;
}

__global__ __launch_bounds__(128, 1) void birnn_main(
    const float* __restrict__ x,
    const float* __restrict__ w_ih_f, const float* __restrict__ w_hh_f,
    const float* __restrict__ b_ih_f, const float* __restrict__ b_hh_f,
    const float* __restrict__ w_ih_b, const float* __restrict__ w_hh_b,
    const float* __restrict__ b_ih_b, const float* __restrict__ b_hh_b,
    const float* __restrict__ w_fc,
    float* __restrict__ out)
{
    // per-warp double-buffered h: plain 64 floats per phase (k-packed consumers)
    __shared__ __align__(16) float hbuf[4][2][HH];
    __shared__ float pbuf[4][32 * 33];   // per-warp fc-dot partials (padded)

    const int wid  = threadIdx.x >> 5;
    const int lane = threadIdx.x & 31;
    const int chain = blockIdx.x * 4 + wid;   // 0..511
    const int dir = chain >> 8;               // 0 = fwd, 1 = bwd
    const int b   = chain & 255;

    const float* wih = dir ? w_ih_b : w_ih_f;
    const float* whh = dir ? w_hh_b : w_hh_f;
    const float* bih = dir ? b_ih_b : b_ih_f;
    const float* bhh = dir ? b_hh_b : b_hh_f;

    const int r0 = 2 * lane, r1 = 2 * lane + 1;   // rows owned by this thread

    // --- recurrent weights, k-paired: wa[m] = (W[r0][2m], W[r0][2m+1]) ---
    ull wa[32], wb[32];
    {
        const ull* rowA = reinterpret_cast<const ull*>(whh + r0 * HH);
        const ull* rowB = reinterpret_cast<const ull*>(whh + r1 * HH);
#pragma unroll
        for (int m = 0; m < 32; m++) { wa[m] = rowA[m]; wb[m] = rowB[m]; }
    }
    const float wihA = wih[r0], wihB = wih[r1];
    const float biasA = bih[r0] + bhh[r0], biasB = bih[r1] + bhh[r1];
    const float wfa = w_fc[r0], wfb = w_fc[r1];

    // h = 0 into phase 0
    reinterpret_cast<float2*>(&hbuf[wid][0][0])[lane] = make_float2(0.f, 0.f);

    float h0 = 0.f, h1 = 0.f;
    const float* xb = x + b * TT;

    // prefetch x for chunk 0
    float xcur = xb[dir ? (TT - 32 + lane) : lane];

    for (int chunk = 0; chunk < NCHUNK; chunk++) {
        const int tb = dir ? (TT - 1 - chunk * 32) : (chunk * 32);
        int nc = (chunk + 1 < NCHUNK) ? (chunk + 1) : chunk;
        float xnext = xb[dir ? (TT - 1 - nc * 32 - 31 + lane) : (nc * 32 + lane)];

#define STEP(SS, RD, WR)                                                          \
        {                                                                         \
            const int s = (SS);                                                   \
            float xs = __shfl_sync(0xffffffffu, xcur, dir ? (31 - s) : s);        \
            float initA = fmaf(xs, wihA, biasA);                                  \
            float initB = fmaf(xs, wihB, biasB);                                  \
            __syncwarp();                                                         \
            const ulonglong2* hr =                                                \
                reinterpret_cast<const ulonglong2*>(&hbuf[wid][RD][0]);           \
            ull a0 = 0, a1 = 0, a2 = 0, a3 = 0;                                   \
            ull c0 = 0, c1 = 0, c2 = 0, c3 = 0;                                   \
            _Pragma("unroll")                                                     \
            for (int k = 0; k < 16; k += 2) {                                     \
                ulonglong2 v = hr[k];                                             \
                ulonglong2 w = hr[k + 1];                                         \
                a0 = fma2(wa[2 * k + 0], v.x, a0);                                \
                a1 = fma2(wa[2 * k + 1], v.y, a1);                                \
                c0 = fma2(wb[2 * k + 0], v.x, c0);                                \
                c1 = fma2(wb[2 * k + 1], v.y, c1);                                \
                a2 = fma2(wa[2 * k + 2], w.x, a2);                                \
                a3 = fma2(wa[2 * k + 3], w.y, a3);                                \
                c2 = fma2(wb[2 * k + 2], w.x, c2);                                \
                c3 = fma2(wb[2 * k + 3], w.y, c3);                                \
            }                                                                     \
            ull sA = add2(add2(a0, a1), add2(a2, a3));                            \
            ull sB = add2(add2(c0, c1), add2(c2, c3));                            \
            float lA, hA, lB, hB;                                                 \
            unpack2(sA, lA, hA);                                                  \
            unpack2(sB, lB, hB);                                                  \
            h0 = tanh_fast(lA + hA + initA);                                      \
            h1 = tanh_fast(lB + hB + initB);                                      \
            reinterpret_cast<float2*>(&hbuf[wid][WR][0])[lane] =                  \
                make_float2(h0, h1);                                              \
            pbuf[wid][s * 33 + lane] = fmaf(h1, wfb, h0 * wfa);                   \
        }

#pragma unroll 1
        for (int s2 = 0; s2 < 16; s2++) {
            STEP(2 * s2,     0, 1)
            STEP(2 * s2 + 1, 1, 0)
        }
#undef STEP

        __syncwarp();
        // transpose-reduce fc partials: lane l produces dot for step s=l of this chunk
        {
            const float* pr = &pbuf[wid][lane * 33];
            float v[32];
#pragma unroll
            for (int j = 0; j < 32; j++) v[j] = pr[j];
#pragma unroll
            for (int st = 16; st >= 1; st >>= 1)
#pragma unroll
                for (int j = 0; j < 32; j++)
                    if (j < st) v[j] = v[j] + v[j + st];
            int tt = dir ? (tb - lane) : (tb + lane);
            g_dot[dir * (BB * TT) + b * TT + tt] = v[0];
        }
        xcur = xnext;
    }

    // final hidden state h_n[dir][b][2l], h_n[dir][b][2l+1]
    reinterpret_cast<float2*>(out + BB * TT + dir * (BB * HH) + b * HH)[lane] =
        make_float2(h0, h1);
}

__global__ void birnn_combine(const float* __restrict__ b_fc, float* __restrict__ out)
{
    int i = blockIdx.x * blockDim.x + threadIdx.x;  // 0 .. B*T/4-1
    const float4* df = reinterpret_cast<const float4*>(g_dot);
    const float4* db = reinterpret_cast<const float4*>(g_dot + BB * TT);
    float4 f = df[i], g = db[i];
    float bias = b_fc[0];
    float4 o;
    {
        float z, e, r;
        z = 0.5f * (f.x + g.x) + bias;
        asm("ex2.approx.f32 %0, %1;" : "=f"(e) : "f"(-1.4426950408889634f * z));
        asm("rcp.approx.f32 %0, %1;" : "=f"(r) : "f"(1.0f + e));
        o.x = r;
        z = 0.5f * (f.y + g.y) + bias;
        asm("ex2.approx.f32 %0, %1;" : "=f"(e) : "f"(-1.4426950408889634f * z));
        asm("rcp.approx.f32 %0, %1;" : "=f"(r) : "f"(1.0f + e));
        o.y = r;
        z = 0.5f * (f.z + g.z) + bias;
        asm("ex2.approx.f32 %0, %1;" : "=f"(e) : "f"(-1.4426950408889634f * z));
        asm("rcp.approx.f32 %0, %1;" : "=f"(r) : "f"(1.0f + e));
        o.z = r;
        z = 0.5f * (f.w + g.w) + bias;
        asm("ex2.approx.f32 %0, %1;" : "=f"(e) : "f"(-1.4426950408889634f * z));
        asm("rcp.approx.f32 %0, %1;" : "=f"(r) : "f"(1.0f + e));
        o.w = r;
    }
    reinterpret_cast<float4*>(out)[i] = o;
}

extern "C" void kernel_launch(void* const* d_in, const int* in_sizes, int n_in,
                              void* d_out, int out_size)
{
    const float* x      = (const float*)d_in[0];
    const float* w_ih_f = (const float*)d_in[1];
    const float* w_hh_f = (const float*)d_in[2];
    const float* b_ih_f = (const float*)d_in[3];
    const float* b_hh_f = (const float*)d_in[4];
    const float* w_ih_b = (const float*)d_in[5];
    const float* w_hh_b = (const float*)d_in[6];
    const float* b_ih_b = (const float*)d_in[7];
    const float* b_hh_b = (const float*)d_in[8];
    const float* w_fc   = (const float*)d_in[9];
    const float* b_fc   = (const float*)d_in[10];
    float* out = (float*)d_out;

    birnn_main<<<128, 128>>>(x, w_ih_f, w_hh_f, b_ih_f, b_hh_f,
                             w_ih_b, w_hh_b, b_ih_b, b_hh_b, w_fc, out);
    birnn_combine<<<(BB * TT) / 4 / 256, 256>>>(b_fc, out);
}

// round 4
// speedup vs baseline: 1.3771x; 1.0163x over previous
#include <cuda_runtime.h>

#define BB 256
#define TT 2048
#define HH 64
#define NCHUNK (TT / 32)

// scratch for per-(dir,b,t) fc dot products: 4 MB
__device__ float g_dot[2 * BB * TT];

typedef unsigned long long ull;

__device__ __forceinline__ ull pack2(float lo, float hi) {
    ull r; asm("mov.b64 %0, {%1, %2};" : "=l"(r) : "f"(lo), "f"(hi)); return r;
}
__device__ __forceinline__ void unpack2(ull v, float& lo, float& hi) {
    asm("mov.b64 {%0, %1}, %2;" : "=f"(lo), "=f"(hi) : "l"(v));
}
__device__ __forceinline__ ull fma2(ull a, ull b, ull c) {
    ull d; asm("fma.rn.f32x2 %0, %1, %2, %3;" : "=l"(d) : "l"(a), "l"(b), "l"(c)); return d;
}
__device__ __forceinline__ ull add2(ull a, ull b) {
    ull d; asm("add.rn.f32x2 %0, %1, %2;" : "=l"(d) : "l"(a), "l"(b)); return d;
}
__device__ __forceinline__ float tanh_fast(float z) {
    float r; asm("tanh.approx.f32 %0, %1;" : "=f"(r) : "f"(z)); return r;
}

__global__ __launch_bounds__(128, 1) void birnn_main(
    const float* __restrict__ x,
    const float* __restrict__ w_ih_f, const float* __restrict__ w_hh_f,
    const float* __restrict__ b_ih_f, const float* __restrict__ b_hh_f,
    const float* __restrict__ w_ih_b, const float* __restrict__ w_hh_b,
    const float* __restrict__ b_ih_b, const float* __restrict__ b_hh_b,
    const float* __restrict__ w_fc,
    float* __restrict__ out)
{
    // per-warp double-buffered h: plain 64 floats per phase (k-packed consumers)
    __shared__ __align__(16) float hbuf[4][2][HH];
    __shared__ float pbuf[4][32 * 33];   // per-warp fc-dot partials (padded)

    const int wid  = threadIdx.x >> 5;
    const int lane = threadIdx.x & 31;
    const int chain = blockIdx.x * 4 + wid;   // 0..511
    const int dir = chain >> 8;               // 0 = fwd, 1 = bwd
    const int b   = chain & 255;

    const float* wih = dir ? w_ih_b : w_ih_f;
    const float* whh = dir ? w_hh_b : w_hh_f;
    const float* bih = dir ? b_ih_b : b_ih_f;
    const float* bhh = dir ? b_hh_b : b_hh_f;

    const int r0 = 2 * lane, r1 = 2 * lane + 1;   // rows owned by this thread

    // --- recurrent weights, k-paired: wa[m] = (W[r0][2m], W[r0][2m+1]) ---
    ull wa[32], wb[32];
    {
        const ull* rowA = reinterpret_cast<const ull*>(whh + r0 * HH);
        const ull* rowB = reinterpret_cast<const ull*>(whh + r1 * HH);
#pragma unroll
        for (int m = 0; m < 32; m++) { wa[m] = rowA[m]; wb[m] = rowB[m]; }
    }
    const float wihA = wih[r0], wihB = wih[r1];
    const float biasA = bih[r0] + bhh[r0], biasB = bih[r1] + bhh[r1];
    const float wfa = w_fc[r0], wfb = w_fc[r1];

    // h = 0 into phase 0
    reinterpret_cast<float2*>(&hbuf[wid][0][0])[lane] = make_float2(0.f, 0.f);

    float h0 = 0.f, h1 = 0.f;
    const float* xb = x + b * TT;

    // prefetch x for chunk 0
    float xcur = xb[dir ? (TT - 32 + lane) : lane];

    for (int chunk = 0; chunk < NCHUNK; chunk++) {
        const int tb = dir ? (TT - 1 - chunk * 32) : (chunk * 32);
        int nc = (chunk + 1 < NCHUNK) ? (chunk + 1) : chunk;
        float xnext = xb[dir ? (TT - 1 - nc * 32 - 31 + lane) : (nc * 32 + lane)];

#define STEP(SS, RD, WR)                                                          \
        {                                                                         \
            const int s = (SS);                                                   \
            float xs = __shfl_sync(0xffffffffu, xcur, dir ? (31 - s) : s);        \
            /* fold init (x*w_ih + bias) into accumulator lane 0 */               \
            ull a0 = pack2(fmaf(xs, wihA, biasA), 0.f);                           \
            ull c0 = pack2(fmaf(xs, wihB, biasB), 0.f);                           \
            ull a1 = 0, c1 = 0;                                                   \
            __syncwarp();                                                         \
            const ulonglong2* hr =                                                \
                reinterpret_cast<const ulonglong2*>(&hbuf[wid][RD][0]);           \
            _Pragma("unroll")                                                     \
            for (int k = 0; k < 16; k += 2) {                                     \
                ulonglong2 v = hr[k];                                             \
                ulonglong2 w = hr[k + 1];                                         \
                a0 = fma2(wa[2 * k + 0], v.x, a0);                                \
                c0 = fma2(wb[2 * k + 0], v.x, c0);                                \
                a1 = fma2(wa[2 * k + 1], v.y, a1);                                \
                c1 = fma2(wb[2 * k + 1], v.y, c1);                                \
                a0 = fma2(wa[2 * k + 2], w.x, a0);                                \
                c0 = fma2(wb[2 * k + 2], w.x, c0);                                \
                a1 = fma2(wa[2 * k + 3], w.y, a1);                                \
                c1 = fma2(wb[2 * k + 3], w.y, c1);                                \
            }                                                                     \
            ull sA = add2(a0, a1);                                                \
            ull sB = add2(c0, c1);                                                \
            float lA, hA, lB, hB;                                                 \
            unpack2(sA, lA, hA);                                                  \
            unpack2(sB, lB, hB);                                                  \
            h0 = tanh_fast(lA + hA);                                              \
            h1 = tanh_fast(lB + hB);                                              \
            reinterpret_cast<float2*>(&hbuf[wid][WR][0])[lane] =                  \
                make_float2(h0, h1);                                              \
            pbuf[wid][s * 33 + lane] = fmaf(h1, wfb, h0 * wfa);                   \
        }

#pragma unroll 1
        for (int s2 = 0; s2 < 16; s2++) {
            STEP(2 * s2,     0, 1)
            STEP(2 * s2 + 1, 1, 0)
        }
#undef STEP

        __syncwarp();
        // transpose-reduce fc partials: lane l produces dot for step s=l of this chunk
        {
            const float* pr = &pbuf[wid][lane * 33];
            float v[32];
#pragma unroll
            for (int j = 0; j < 32; j++) v[j] = pr[j];
#pragma unroll
            for (int st = 16; st >= 1; st >>= 1)
#pragma unroll
                for (int j = 0; j < 32; j++)
                    if (j < st) v[j] = v[j] + v[j + st];
            int tt = dir ? (tb - lane) : (tb + lane);
            g_dot[dir * (BB * TT) + b * TT + tt] = v[0];
        }
        xcur = xnext;
    }

    // final hidden state h_n[dir][b][2l], h_n[dir][b][2l+1]
    reinterpret_cast<float2*>(out + BB * TT + dir * (BB * HH) + b * HH)[lane] =
        make_float2(h0, h1);
}

__global__ void birnn_combine(const float* __restrict__ b_fc, float* __restrict__ out)
{
    int i = blockIdx.x * blockDim.x + threadIdx.x;  // 0 .. B*T/4-1
    const float4* df = reinterpret_cast<const float4*>(g_dot);
    const float4* db = reinterpret_cast<const float4*>(g_dot + BB * TT);
    float4 f = df[i], g = db[i];
    float bias = b_fc[0];
    float4 o;
    {
        float z, e, r;
        z = 0.5f * (f.x + g.x) + bias;
        asm("ex2.approx.f32 %0, %1;" : "=f"(e) : "f"(-1.4426950408889634f * z));
        asm("rcp.approx.f32 %0, %1;" : "=f"(r) : "f"(1.0f + e));
        o.x = r;
        z = 0.5f * (f.y + g.y) + bias;
        asm("ex2.approx.f32 %0, %1;" : "=f"(e) : "f"(-1.4426950408889634f * z));
        asm("rcp.approx.f32 %0, %1;" : "=f"(r) : "f"(1.0f + e));
        o.y = r;
        z = 0.5f * (f.z + g.z) + bias;
        asm("ex2.approx.f32 %0, %1;" : "=f"(e) : "f"(-1.4426950408889634f * z));
        asm("rcp.approx.f32 %0, %1;" : "=f"(r) : "f"(1.0f + e));
        o.z = r;
        z = 0.5f * (f.w + g.w) + bias;
        asm("ex2.approx.f32 %0, %1;" : "=f"(e) : "f"(-1.4426950408889634f * z));
        asm("rcp.approx.f32 %0, %1;" : "=f"(r) : "f"(1.0f + e));
        o.w = r;
    }
    reinterpret_cast<float4*>(out)[i] = o;
}

extern "C" void kernel_launch(void* const* d_in, const int* in_sizes, int n_in,
                              void* d_out, int out_size)
{
    const float* x      = (const float*)d_in[0];
    const float* w_ih_f = (const float*)d_in[1];
    const float* w_hh_f = (const float*)d_in[2];
    const float* b_ih_f = (const float*)d_in[3];
    const float* b_hh_f = (const float*)d_in[4];
    const float* w_ih_b = (const float*)d_in[5];
    const float* w_hh_b = (const float*)d_in[6];
    const float* b_ih_b = (const float*)d_in[7];
    const float* b_hh_b = (const float*)d_in[8];
    const float* w_fc   = (const float*)d_in[9];
    const float* b_fc   = (const float*)d_in[10];
    float* out = (float*)d_out;

    birnn_main<<<128, 128>>>(x, w_ih_f, w_hh_f, b_ih_f, b_hh_f,
                             w_ih_b, w_hh_b, b_ih_b, b_hh_b, w_fc, out);
    birnn_combine<<<(BB * TT) / 4 / 256, 256>>>(b_fc, out);
}